// round 14
// baseline (speedup 1.0000x reference)
#include <cuda_runtime.h>
#include <math.h>
#include <stdint.h>

// Problem dims (fixed by the benchmark)
#define LDIM 2048
#define BDIM 4
#define EDIM 1024
#define HDIM 16
#define DDIM 64
#define MROWS (LDIM * BDIM)   // 8192
#define E3    (3 * EDIM)      // 3072

// Scratch (allocation-free rule: __device__ globals)
__device__ float g_qkv[(size_t)MROWS * E3];    // [L*B, 3E], q pre-scaled
__device__ float g_attn[(size_t)MROWS * EDIM]; // [L*B, E]

// ---------------------------------------------------------------------------
// tf32 helpers
// ---------------------------------------------------------------------------
__device__ __forceinline__ uint32_t f2tf(float f) {
    uint32_t u;
    asm("cvt.rna.tf32.f32 %0, %1;" : "=r"(u) : "f"(f));
    return u;
}

__device__ __forceinline__ void mma_tf32(float c[4],
    uint32_t a0, uint32_t a1, uint32_t a2, uint32_t a3,
    uint32_t b0, uint32_t b1)
{
    asm volatile(
        "mma.sync.aligned.m16n8k8.row.col.f32.tf32.tf32.f32 "
        "{%0,%1,%2,%3}, {%4,%5,%6,%7}, {%8,%9}, {%0,%1,%2,%3};\n"
        : "+f"(c[0]), "+f"(c[1]), "+f"(c[2]), "+f"(c[3])
        : "r"(a0), "r"(a1), "r"(a2), "r"(a3), "r"(b0), "r"(b1));
}

// Paired-column layout within each 8-col block: word order
//   [c0, c4, c1, c5, c2, c6, c3, c7]
// so the fragment pair (col t, col t+4) = adjacent words = one LDS.64.
// Staging an 8-block from two float4s (v0 = cols 0-3, v1 = cols 4-7):
//   u1 = (v0.x, v1.x, v0.y, v1.y), u2 = (v0.z, v1.z, v0.w, v1.w)
__device__ __forceinline__ uint4 perm_lo(const float4& v0, const float4& v1) {
    uint4 u; u.x = f2tf(v0.x); u.y = f2tf(v1.x); u.z = f2tf(v0.y); u.w = f2tf(v1.y);
    return u;
}
__device__ __forceinline__ uint4 perm_hi(const float4& v0, const float4& v1) {
    uint4 u; u.x = f2tf(v0.z); u.y = f2tf(v1.z); u.z = f2tf(v0.w); u.w = f2tf(v1.w);
    return u;
}

// ---------------------------------------------------------------------------
// tf32 tensor GEMM: C[m,n] = sum_k A[m,k]*W[n,k] + bias[n]
// CTA 128x128, BK=16, 8 warps each m64 x n32. Double-buffered smem.
// Stride GS=24 (== 8 mod 32): paired LDS.64 fragment loads conflict-free.
// Staging: one 8-col block per thread per operand -> 2x STS.128 each.
// ---------------------------------------------------------------------------
#define GS 24

template <int SCALE_COLS>
__global__ __launch_bounds__(256) void gemm_tf32(
    const float* __restrict__ A, const float* __restrict__ W,
    const float* __restrict__ bias, float* __restrict__ C,
    int Nn, int Kn)
{
    __shared__ uint32_t As[2][128 * GS];
    __shared__ uint32_t Bs[2][128 * GS];

    const int tid  = threadIdx.x;
    const int w    = tid >> 5;
    const int lane = tid & 31;
    const int gr   = lane >> 2;
    const int tg   = lane & 3;
    const int wm   = (w >> 2) * 64;   // 0 or 64
    const int wn   = (w & 3) * 32;    // 0,32,64,96
    const int n0   = blockIdx.x * 128;
    const int m0   = blockIdx.y * 128;

    // staging: one 8-col block of A and one of B per thread per BK16 tile
    const int srow = tid >> 1;            // 0..127
    const int skb  = (tid & 1) * 8;       // 0 or 8

    const float* Ap = A + (size_t)(m0 + srow) * Kn + skb;
    const float* Wp = W + (size_t)(n0 + srow) * Kn + skb;

    float acc[4][4][4] = {};

    const int nK = Kn >> 4;
    float4 av0 = *(const float4*)(Ap);
    float4 av1 = *(const float4*)(Ap + 4);
    float4 wv0 = *(const float4*)(Wp);
    float4 wv1 = *(const float4*)(Wp + 4);

    for (int kt = 0; kt < nK; kt++) {
        const int buf = kt & 1;
        // stage: interleaved STS.128 pairs
        *(uint4*)&As[buf][srow * GS + skb]     = perm_lo(av0, av1);
        *(uint4*)&As[buf][srow * GS + skb + 4] = perm_hi(av0, av1);
        *(uint4*)&Bs[buf][srow * GS + skb]     = perm_lo(wv0, wv1);
        *(uint4*)&Bs[buf][srow * GS + skb + 4] = perm_hi(wv0, wv1);
        __syncthreads();

        // prefetch next BK16 tile
        if (kt + 1 < nK) {
            const int ko = (kt + 1) << 4;
            av0 = *(const float4*)(Ap + ko);
            av1 = *(const float4*)(Ap + ko + 4);
            wv0 = *(const float4*)(Wp + ko);
            wv1 = *(const float4*)(Wp + ko + 4);
        }

        // compute: 2 k8 steps, LDS.64 paired fragments
        #pragma unroll
        for (int k8 = 0; k8 < 16; k8 += 8) {
            uint2 alo[4], ahi[4], bb[4];
            #pragma unroll
            for (int i = 0; i < 4; i++) {
                const int mr = wm + 16 * i + gr;
                alo[i] = *(const uint2*)&As[buf][(mr)     * GS + k8 + 2 * tg];
                ahi[i] = *(const uint2*)&As[buf][(mr + 8) * GS + k8 + 2 * tg];
            }
            #pragma unroll
            for (int j = 0; j < 4; j++) {
                const int nr = wn + 8 * j + gr;
                bb[j] = *(const uint2*)&Bs[buf][nr * GS + k8 + 2 * tg];
            }
            #pragma unroll
            for (int i = 0; i < 4; i++)
                #pragma unroll
                for (int j = 0; j < 4; j++)
                    mma_tf32(acc[i][j], alo[i].x, ahi[i].x, alo[i].y, ahi[i].y,
                             bb[j].x, bb[j].y);
        }
    }

    // epilogue: bias + optional q-scaling
    #pragma unroll
    for (int i = 0; i < 4; i++) {
        const int row = m0 + wm + 16 * i + gr;
        #pragma unroll
        for (int j = 0; j < 4; j++) {
            const int col = n0 + wn + 8 * j + 2 * tg;
            const float b0v = bias[col], b1v = bias[col + 1];
            float s = (SCALE_COLS > 0 && col < SCALE_COLS) ? 0.125f : 1.0f;
            float2 lo = make_float2((acc[i][j][0] + b0v) * s,
                                    (acc[i][j][1] + b1v) * s);
            float2 hi = make_float2((acc[i][j][2] + b0v) * s,
                                    (acc[i][j][3] + b1v) * s);
            *(float2*)(C + (size_t)row * Nn + col) = lo;
            *(float2*)(C + (size_t)(row + 8) * Nn + col) = hi;
        }
    }
}

// ---------------------------------------------------------------------------
// Flash attention, tf32 mma.sync.
//  - Qs/Ks paired-column (LDS.64 fragments), STS.128 staging, stride 72.
//  - V stored d-major (Vt): PV B-fragments = one LDS.64 (adjacent keys),
//    conflict-free (stride 72 == 8 mod 32).
//  - P stays in registers; S-accumulator fragment reused DIRECTLY as PV
//    A-fragment via the key permutation pi(l) = 2(l%4)+(l/4): a = (c0,c2,c1,c3).
//    No shuffles, no P smem.
//  - 74 KB smem -> 2 CTAs/SM.
// ---------------------------------------------------------------------------
#define AS2 72

__global__ __launch_bounds__(256, 2) void attn_tf32(
    const float* __restrict__ qkv, const unsigned char* __restrict__ kpm,
    float* __restrict__ outp)
{
    extern __shared__ uint32_t sm[];
    uint32_t* Qs = sm;                  // [128][72] permuted tf32
    uint32_t* Ks = Qs + 128 * AS2;      // [64][72]  permuted, key rows
    uint32_t* Vt = Ks + 64 * AS2;       // [64 d][72] plain, d-major (V^T)
    float* maskAdd = (float*)(Vt + 64 * AS2);   // [64]

    const int tid  = threadIdx.x;
    const int w    = tid >> 5;
    const int lane = tid & 31;
    const int gr   = lane >> 2;
    const int tg   = lane & 3;
    const int q0   = w * 16;
    const int m0   = blockIdx.x * 128;
    const int bh   = blockIdx.y;
    const int b    = bh >> 4;
    const int h    = bh & 15;
    const int hoff = h * 64;

    // ---- stage Q (paired blocks, STS.128); q pre-scaled in projection ----
    #pragma unroll
    for (int p = 0; p < 4; p++) {
        int row = (tid >> 2) + (p & 1) * 64;
        int kb  = (tid & 3) * 8 + (p >> 1) * 32;
        const float* src = qkv + (size_t)((m0 + row) * BDIM + b) * E3 + hoff + kb;
        float4 v0 = *(const float4*)(src);
        float4 v1 = *(const float4*)(src + 4);
        *(uint4*)&Qs[row * AS2 + kb]     = perm_lo(v0, v1);
        *(uint4*)&Qs[row * AS2 + kb + 4] = perm_hi(v0, v1);
    }

    const int vkey = tid & 63;            // V staging: key == lane mod 32 -> conflict-free
    const int vc0  = (tid >> 6) * 4;

    float o[8][4] = {};
    float m_lo = -INFINITY, m_hi = -INFINITY;
    float l_lo = 0.f, l_hi = 0.f;

    for (int t = 0; t < LDIM / 64; t++) {
        const int s0 = t * 64;
        __syncthreads();   // prior iter's reads of Ks/Vt complete

        // ---- stage K (paired blocks, STS.128) ----
        #pragma unroll
        for (int p = 0; p < 2; p++) {
            int row = tid >> 2;                       // 0..63
            int kb  = (tid & 3) * 8 + p * 32;
            const float* src = qkv + (size_t)((s0 + row) * BDIM + b) * E3
                               + hoff + EDIM + kb;
            float4 v0 = *(const float4*)(src);
            float4 v1 = *(const float4*)(src + 4);
            *(uint4*)&Ks[row * AS2 + kb]     = perm_lo(v0, v1);
            *(uint4*)&Ks[row * AS2 + kb + 4] = perm_hi(v0, v1);
        }
        // ---- stage V transposed (d-major); scalar stores, banks 8i+key ----
        #pragma unroll
        for (int p = 0; p < 4; p++) {
            int c4 = vc0 + p * 16;
            float4 v = *(const float4*)(qkv + (size_t)((s0 + vkey) * BDIM + b) * E3
                                        + hoff + 2 * EDIM + c4);
            Vt[(c4 + 0) * AS2 + vkey] = f2tf(v.x);
            Vt[(c4 + 1) * AS2 + vkey] = f2tf(v.y);
            Vt[(c4 + 2) * AS2 + vkey] = f2tf(v.z);
            Vt[(c4 + 3) * AS2 + vkey] = f2tf(v.w);
        }
        if (tid < 64)
            maskAdd[tid] = kpm[(size_t)(s0 + tid) * BDIM + b] ? -INFINITY : 0.f;
        __syncthreads();

        // ---- S = Q K^T : m16 x n64 x k64 per warp (LDS.64 fragments) ----
        float c[8][4] = {};
        #pragma unroll
        for (int k8 = 0; k8 < 64; k8 += 8) {
            uint2 alo = *(const uint2*)&Qs[(q0 + gr)     * AS2 + k8 + 2 * tg];
            uint2 ahi = *(const uint2*)&Qs[(q0 + gr + 8) * AS2 + k8 + 2 * tg];
            #pragma unroll
            for (int j = 0; j < 8; j++) {
                uint2 bb = *(const uint2*)&Ks[(8 * j + gr) * AS2 + k8 + 2 * tg];
                mma_tf32(c[j], alo.x, ahi.x, alo.y, ahi.y, bb.x, bb.y);
            }
        }

        // ---- key-padding mask (S col = 8j + 2tg, 2tg+1) ----
        #pragma unroll
        for (int j = 0; j < 8; j++) {
            float ma0 = maskAdd[8 * j + 2 * tg];
            float ma1 = maskAdd[8 * j + 2 * tg + 1];
            c[j][0] += ma0; c[j][1] += ma1;
            c[j][2] += ma0; c[j][3] += ma1;
        }

        // ---- online softmax ----
        float mx_lo = -INFINITY, mx_hi = -INFINITY;
        #pragma unroll
        for (int j = 0; j < 8; j++) {
            mx_lo = fmaxf(mx_lo, fmaxf(c[j][0], c[j][1]));
            mx_hi = fmaxf(mx_hi, fmaxf(c[j][2], c[j][3]));
        }
        mx_lo = fmaxf(mx_lo, __shfl_xor_sync(0xffffffffu, mx_lo, 1));
        mx_lo = fmaxf(mx_lo, __shfl_xor_sync(0xffffffffu, mx_lo, 2));
        mx_hi = fmaxf(mx_hi, __shfl_xor_sync(0xffffffffu, mx_hi, 1));
        mx_hi = fmaxf(mx_hi, __shfl_xor_sync(0xffffffffu, mx_hi, 2));

        float mn_lo = fmaxf(m_lo, mx_lo);
        float mn_hi = fmaxf(m_hi, mx_hi);
        float mr_lo = (mn_lo == -INFINITY) ? 0.f : mn_lo;
        float mr_hi = (mn_hi == -INFINITY) ? 0.f : mn_hi;

        uint32_t cp[8][4];   // tf32 bits of P (register-resident)
        float sum_lo = 0.f, sum_hi = 0.f;
        #pragma unroll
        for (int j = 0; j < 8; j++) {
            float p0 = __expf(c[j][0] - mr_lo);
            float p1 = __expf(c[j][1] - mr_lo);
            float p2 = __expf(c[j][2] - mr_hi);
            float p3 = __expf(c[j][3] - mr_hi);
            sum_lo += p0 + p1;
            sum_hi += p2 + p3;
            cp[j][0] = f2tf(p0); cp[j][1] = f2tf(p1);
            cp[j][2] = f2tf(p2); cp[j][3] = f2tf(p3);
        }
        sum_lo += __shfl_xor_sync(0xffffffffu, sum_lo, 1);
        sum_lo += __shfl_xor_sync(0xffffffffu, sum_lo, 2);
        sum_hi += __shfl_xor_sync(0xffffffffu, sum_hi, 1);
        sum_hi += __shfl_xor_sync(0xffffffffu, sum_hi, 2);

        float sc_lo = (m_lo == -INFINITY) ? 0.f : __expf(m_lo - mr_lo);
        float sc_hi = (m_hi == -INFINITY) ? 0.f : __expf(m_hi - mr_hi);
        l_lo = l_lo * sc_lo + sum_lo;
        l_hi = l_hi * sc_hi + sum_hi;
        m_lo = mn_lo;
        m_hi = mn_hi;

        #pragma unroll
        for (int j = 0; j < 8; j++) {
            o[j][0] *= sc_lo; o[j][1] *= sc_lo;
            o[j][2] *= sc_hi; o[j][3] *= sc_hi;
        }

        // ---- O += P V : S-fragment reused as A-fragment (keys permuted by
        //      pi(l)=2(l%4)+(l/4)); B = Vt rows d, adjacent keys -> LDS.64 ----
        #pragma unroll
        for (int j = 0; j < 8; j++) {
            const uint32_t a0 = cp[j][0];   // key 8j+2tg,   rows gr
            const uint32_t a1 = cp[j][2];   // key 8j+2tg,   rows gr+8
            const uint32_t a2 = cp[j][1];   // key 8j+2tg+1, rows gr
            const uint32_t a3 = cp[j][3];   // key 8j+2tg+1, rows gr+8
            #pragma unroll
            for (int jj = 0; jj < 8; jj++) {
                uint2 bb = *(const uint2*)&Vt[(8 * jj + gr) * AS2 + 8 * j + 2 * tg];
                mma_tf32(o[jj], a0, a1, a2, a3, bb.x, bb.y);
            }
        }
    }

    // ---- normalize + write out [L*B, E] at head offset ----
    float il_lo = 1.f / l_lo;
    float il_hi = 1.f / l_hi;
    #pragma unroll
    for (int j = 0; j < 8; j++) {
        float2 vlo = make_float2(o[j][0] * il_lo, o[j][1] * il_lo);
        *(float2*)(outp + (size_t)((m0 + q0 + gr) * BDIM + b) * EDIM
                   + hoff + 8 * j + 2 * tg) = vlo;
        float2 vhi = make_float2(o[j][2] * il_hi, o[j][3] * il_hi);
        *(float2*)(outp + (size_t)((m0 + q0 + gr + 8) * BDIM + b) * EDIM
                   + hoff + 8 * j + 2 * tg) = vhi;
    }
}

// ---------------------------------------------------------------------------
extern "C" void kernel_launch(void* const* d_in, const int* in_sizes, int n_in,
                              void* d_out, int out_size)
{
    const float* x    = (const float*)d_in[0];
    const float* win  = (const float*)d_in[1];
    const float* bin  = (const float*)d_in[2];
    const float* wout = (const float*)d_in[3];
    const float* bout = (const float*)d_in[4];
    const unsigned char* kpm = (const unsigned char*)d_in[5];
    float* out = (float*)d_out;

    float *qkv_ptr, *attn_ptr;
    cudaGetSymbolAddress((void**)&qkv_ptr,  g_qkv);
    cudaGetSymbolAddress((void**)&attn_ptr, g_attn);

    // 1) QKV projection (tf32 tensor; q pre-scaled by D^-0.5 in epilogue)
    {
        dim3 grid(E3 / 128, MROWS / 128);
        gemm_tf32<EDIM><<<grid, 256>>>(x, win, bin, qkv_ptr, E3, EDIM);
    }

    // 2) Flash attention (tf32 tensor, 2 CTAs/SM)
    {
        int smem = (128 * AS2 + 64 * AS2 + 64 * AS2) * (int)sizeof(uint32_t)
                   + 64 * (int)sizeof(float);   // 73984 B
        cudaFuncSetAttribute(attn_tf32, cudaFuncAttributeMaxDynamicSharedMemorySize, smem);
        dim3 grid(LDIM / 128, BDIM * HDIM);
        attn_tf32<<<grid, 256, smem>>>(qkv_ptr, kpm, attn_ptr);
    }

    // 3) Output projection (tf32 tensor)
    {
        dim3 grid(EDIM / 128, MROWS / 128);
        gemm_tf32<0><<<grid, 256>>>(attn_ptr, wout, bout, out, EDIM, EDIM);
    }
}

// round 16
// speedup vs baseline: 1.1103x; 1.1103x over previous
#include <cuda_runtime.h>
#include <math.h>
#include <stdint.h>

// Problem dims (fixed by the benchmark)
#define LDIM 2048
#define BDIM 4
#define EDIM 1024
#define HDIM 16
#define DDIM 64
#define MROWS (LDIM * BDIM)   // 8192
#define E3    (3 * EDIM)      // 3072

// Scratch (allocation-free rule: __device__ globals)
__device__ float g_qkv[(size_t)MROWS * E3];    // [L*B, 3E], q pre-scaled
__device__ float g_attn[(size_t)MROWS * EDIM]; // [L*B, E]

// ---------------------------------------------------------------------------
// tf32 helpers
// ---------------------------------------------------------------------------
__device__ __forceinline__ uint32_t f2tf(float f) {
    uint32_t u;
    asm("cvt.rna.tf32.f32 %0, %1;" : "=r"(u) : "f"(f));
    return u;
}

__device__ __forceinline__ void mma_tf32(float c[4],
    uint32_t a0, uint32_t a1, uint32_t a2, uint32_t a3,
    uint32_t b0, uint32_t b1)
{
    asm volatile(
        "mma.sync.aligned.m16n8k8.row.col.f32.tf32.tf32.f32 "
        "{%0,%1,%2,%3}, {%4,%5,%6,%7}, {%8,%9}, {%0,%1,%2,%3};\n"
        : "+f"(c[0]), "+f"(c[1]), "+f"(c[2]), "+f"(c[3])
        : "r"(a0), "r"(a1), "r"(a2), "r"(a3), "r"(b0), "r"(b1));
}

// ---------------------------------------------------------------------------
// tf32 tensor GEMM (R7 configuration — measured fastest at 400us for QKV):
// C[m,n] = sum_k A[m,k]*W[n,k] + bias[n]
// CTA tile 128x128, BK=16, 8 warps each m64 x n32. Double-buffered smem,
// stride 20 (=4 mod 32) -> conflict-free scalar fragment loads,
// 16B-aligned rows for STS.128 staging.
// ---------------------------------------------------------------------------
#define GS 20

template <int SCALE_COLS>
__global__ __launch_bounds__(256) void gemm_tf32(
    const float* __restrict__ A, const float* __restrict__ W,
    const float* __restrict__ bias, float* __restrict__ C,
    int Nn, int Kn)
{
    __shared__ uint32_t As[2][128 * GS];
    __shared__ uint32_t Bs[2][128 * GS];

    const int tid  = threadIdx.x;
    const int w    = tid >> 5;
    const int lane = tid & 31;
    const int gr   = lane >> 2;
    const int tg   = lane & 3;
    const int wm   = (w >> 2) * 64;   // 0 or 64
    const int wn   = (w & 3) * 32;    // 0,32,64,96
    const int n0   = blockIdx.x * 128;
    const int m0   = blockIdx.y * 128;

    // staging: each thread owns 2 float4 of A and 2 of B per BK16 tile
    const int r0 = tid >> 2;              // 0..63
    const int r1 = r0 + 64;               // 64..127
    const int c4 = (tid & 3) * 4;         // 0,4,8,12

    const float* Ap0 = A + (size_t)(m0 + r0) * Kn + c4;
    const float* Ap1 = A + (size_t)(m0 + r1) * Kn + c4;
    const float* Wp0 = W + (size_t)(n0 + r0) * Kn + c4;
    const float* Wp1 = W + (size_t)(n0 + r1) * Kn + c4;

    float acc[4][4][4] = {};

    const int nK = Kn >> 4;
    float4 av0 = *(const float4*)Ap0;
    float4 av1 = *(const float4*)Ap1;
    float4 wv0 = *(const float4*)Wp0;
    float4 wv1 = *(const float4*)Wp1;

    for (int kt = 0; kt < nK; kt++) {
        const int buf = kt & 1;
        // stage (convert to tf32, STS.128 via uint4)
        {
            uint4 u;
            u.x = f2tf(av0.x); u.y = f2tf(av0.y); u.z = f2tf(av0.z); u.w = f2tf(av0.w);
            *(uint4*)&As[buf][r0 * GS + c4] = u;
            u.x = f2tf(av1.x); u.y = f2tf(av1.y); u.z = f2tf(av1.z); u.w = f2tf(av1.w);
            *(uint4*)&As[buf][r1 * GS + c4] = u;
            u.x = f2tf(wv0.x); u.y = f2tf(wv0.y); u.z = f2tf(wv0.z); u.w = f2tf(wv0.w);
            *(uint4*)&Bs[buf][r0 * GS + c4] = u;
            u.x = f2tf(wv1.x); u.y = f2tf(wv1.y); u.z = f2tf(wv1.z); u.w = f2tf(wv1.w);
            *(uint4*)&Bs[buf][r1 * GS + c4] = u;
        }
        __syncthreads();

        // prefetch next BK16 tile
        if (kt + 1 < nK) {
            const int ko = (kt + 1) << 4;
            av0 = *(const float4*)(Ap0 + ko);
            av1 = *(const float4*)(Ap1 + ko);
            wv0 = *(const float4*)(Wp0 + ko);
            wv1 = *(const float4*)(Wp1 + ko);
        }

        // compute: 2 k8 steps, scalar conflict-free fragment loads
        #pragma unroll
        for (int k8 = 0; k8 < 16; k8 += 8) {
            uint32_t a[4][4], bfr[4][2];
            #pragma unroll
            for (int i = 0; i < 4; i++) {
                const int mr = wm + 16 * i + gr;
                a[i][0] = As[buf][(mr)     * GS + k8 + tg];
                a[i][1] = As[buf][(mr + 8) * GS + k8 + tg];
                a[i][2] = As[buf][(mr)     * GS + k8 + tg + 4];
                a[i][3] = As[buf][(mr + 8) * GS + k8 + tg + 4];
            }
            #pragma unroll
            for (int j = 0; j < 4; j++) {
                const int nr = wn + 8 * j + gr;
                bfr[j][0] = Bs[buf][nr * GS + k8 + tg];
                bfr[j][1] = Bs[buf][nr * GS + k8 + tg + 4];
            }
            #pragma unroll
            for (int i = 0; i < 4; i++)
                #pragma unroll
                for (int j = 0; j < 4; j++)
                    mma_tf32(acc[i][j], a[i][0], a[i][1], a[i][2], a[i][3],
                             bfr[j][0], bfr[j][1]);
        }
    }

    // epilogue: bias + optional q-scaling
    #pragma unroll
    for (int i = 0; i < 4; i++) {
        const int row = m0 + wm + 16 * i + gr;
        #pragma unroll
        for (int j = 0; j < 4; j++) {
            const int col = n0 + wn + 8 * j + 2 * tg;
            const float b0v = bias[col], b1v = bias[col + 1];
            float s = (SCALE_COLS > 0 && col < SCALE_COLS) ? 0.125f : 1.0f;
            float2 lo = make_float2((acc[i][j][0] + b0v) * s,
                                    (acc[i][j][1] + b1v) * s);
            float2 hi = make_float2((acc[i][j][2] + b0v) * s,
                                    (acc[i][j][3] + b1v) * s);
            *(float2*)(C + (size_t)row * Nn + col) = lo;
            *(float2*)(C + (size_t)(row + 8) * Nn + col) = hi;
        }
    }
}

// ---------------------------------------------------------------------------
// Flash attention, tf32 mma.sync (R14 configuration — measured ~570us).
//  - Qs/Ks paired-column (LDS.64 fragments), STS.128 staging, stride 72.
//  - V stored d-major (Vt): PV B-fragments = one LDS.64 (adjacent keys).
//  - P stays in registers; S-accumulator fragment reused DIRECTLY as PV
//    A-fragment via key permutation pi(l)=2(l%4)+(l/4): a=(c0,c2,c1,c3).
//  - 74 KB smem -> 2 CTAs/SM.
// ---------------------------------------------------------------------------
__device__ __forceinline__ uint4 perm_lo(const float4& v0, const float4& v1) {
    uint4 u; u.x = f2tf(v0.x); u.y = f2tf(v1.x); u.z = f2tf(v0.y); u.w = f2tf(v1.y);
    return u;
}
__device__ __forceinline__ uint4 perm_hi(const float4& v0, const float4& v1) {
    uint4 u; u.x = f2tf(v0.z); u.y = f2tf(v1.z); u.z = f2tf(v0.w); u.w = f2tf(v1.w);
    return u;
}

#define AS2 72

__global__ __launch_bounds__(256, 2) void attn_tf32(
    const float* __restrict__ qkv, const unsigned char* __restrict__ kpm,
    float* __restrict__ outp)
{
    extern __shared__ uint32_t sm[];
    uint32_t* Qs = sm;                  // [128][72] permuted tf32
    uint32_t* Ks = Qs + 128 * AS2;      // [64][72]  permuted, key rows
    uint32_t* Vt = Ks + 64 * AS2;       // [64 d][72] plain, d-major (V^T)
    float* maskAdd = (float*)(Vt + 64 * AS2);   // [64]

    const int tid  = threadIdx.x;
    const int w    = tid >> 5;
    const int lane = tid & 31;
    const int gr   = lane >> 2;
    const int tg   = lane & 3;
    const int q0   = w * 16;
    const int m0   = blockIdx.x * 128;
    const int bh   = blockIdx.y;
    const int b    = bh >> 4;
    const int h    = bh & 15;
    const int hoff = h * 64;

    // ---- stage Q (paired blocks, STS.128); q pre-scaled in projection ----
    #pragma unroll
    for (int p = 0; p < 4; p++) {
        int row = (tid >> 2) + (p & 1) * 64;
        int kb  = (tid & 3) * 8 + (p >> 1) * 32;
        const float* src = qkv + (size_t)((m0 + row) * BDIM + b) * E3 + hoff + kb;
        float4 v0 = *(const float4*)(src);
        float4 v1 = *(const float4*)(src + 4);
        *(uint4*)&Qs[row * AS2 + kb]     = perm_lo(v0, v1);
        *(uint4*)&Qs[row * AS2 + kb + 4] = perm_hi(v0, v1);
    }

    const int vkey = tid & 63;            // V staging: conflict-free banks
    const int vc0  = (tid >> 6) * 4;

    float o[8][4] = {};
    float m_lo = -INFINITY, m_hi = -INFINITY;
    float l_lo = 0.f, l_hi = 0.f;

    for (int t = 0; t < LDIM / 64; t++) {
        const int s0 = t * 64;
        __syncthreads();   // prior iter's reads of Ks/Vt complete

        // ---- stage K (paired blocks, STS.128) ----
        #pragma unroll
        for (int p = 0; p < 2; p++) {
            int row = tid >> 2;                       // 0..63
            int kb  = (tid & 3) * 8 + p * 32;
            const float* src = qkv + (size_t)((s0 + row) * BDIM + b) * E3
                               + hoff + EDIM + kb;
            float4 v0 = *(const float4*)(src);
            float4 v1 = *(const float4*)(src + 4);
            *(uint4*)&Ks[row * AS2 + kb]     = perm_lo(v0, v1);
            *(uint4*)&Ks[row * AS2 + kb + 4] = perm_hi(v0, v1);
        }
        // ---- stage V transposed (d-major); scalar stores, banks 8i+key ----
        #pragma unroll
        for (int p = 0; p < 4; p++) {
            int c4 = vc0 + p * 16;
            float4 v = *(const float4*)(qkv + (size_t)((s0 + vkey) * BDIM + b) * E3
                                        + hoff + 2 * EDIM + c4);
            Vt[(c4 + 0) * AS2 + vkey] = f2tf(v.x);
            Vt[(c4 + 1) * AS2 + vkey] = f2tf(v.y);
            Vt[(c4 + 2) * AS2 + vkey] = f2tf(v.z);
            Vt[(c4 + 3) * AS2 + vkey] = f2tf(v.w);
        }
        if (tid < 64)
            maskAdd[tid] = kpm[(size_t)(s0 + tid) * BDIM + b] ? -INFINITY : 0.f;
        __syncthreads();

        // ---- S = Q K^T : m16 x n64 x k64 per warp (LDS.64 fragments) ----
        float c[8][4] = {};
        #pragma unroll
        for (int k8 = 0; k8 < 64; k8 += 8) {
            uint2 alo = *(const uint2*)&Qs[(q0 + gr)     * AS2 + k8 + 2 * tg];
            uint2 ahi = *(const uint2*)&Qs[(q0 + gr + 8) * AS2 + k8 + 2 * tg];
            #pragma unroll
            for (int j = 0; j < 8; j++) {
                uint2 bb = *(const uint2*)&Ks[(8 * j + gr) * AS2 + k8 + 2 * tg];
                mma_tf32(c[j], alo.x, ahi.x, alo.y, ahi.y, bb.x, bb.y);
            }
        }

        // ---- key-padding mask (S col = 8j + 2tg, 2tg+1) ----
        #pragma unroll
        for (int j = 0; j < 8; j++) {
            float ma0 = maskAdd[8 * j + 2 * tg];
            float ma1 = maskAdd[8 * j + 2 * tg + 1];
            c[j][0] += ma0; c[j][1] += ma1;
            c[j][2] += ma0; c[j][3] += ma1;
        }

        // ---- online softmax ----
        float mx_lo = -INFINITY, mx_hi = -INFINITY;
        #pragma unroll
        for (int j = 0; j < 8; j++) {
            mx_lo = fmaxf(mx_lo, fmaxf(c[j][0], c[j][1]));
            mx_hi = fmaxf(mx_hi, fmaxf(c[j][2], c[j][3]));
        }
        mx_lo = fmaxf(mx_lo, __shfl_xor_sync(0xffffffffu, mx_lo, 1));
        mx_lo = fmaxf(mx_lo, __shfl_xor_sync(0xffffffffu, mx_lo, 2));
        mx_hi = fmaxf(mx_hi, __shfl_xor_sync(0xffffffffu, mx_hi, 1));
        mx_hi = fmaxf(mx_hi, __shfl_xor_sync(0xffffffffu, mx_hi, 2));

        float mn_lo = fmaxf(m_lo, mx_lo);
        float mn_hi = fmaxf(m_hi, mx_hi);
        float mr_lo = (mn_lo == -INFINITY) ? 0.f : mn_lo;
        float mr_hi = (mn_hi == -INFINITY) ? 0.f : mn_hi;

        uint32_t cp[8][4];   // tf32 bits of P (register-resident)
        float sum_lo = 0.f, sum_hi = 0.f;
        #pragma unroll
        for (int j = 0; j < 8; j++) {
            float p0 = __expf(c[j][0] - mr_lo);
            float p1 = __expf(c[j][1] - mr_lo);
            float p2 = __expf(c[j][2] - mr_hi);
            float p3 = __expf(c[j][3] - mr_hi);
            sum_lo += p0 + p1;
            sum_hi += p2 + p3;
            cp[j][0] = f2tf(p0); cp[j][1] = f2tf(p1);
            cp[j][2] = f2tf(p2); cp[j][3] = f2tf(p3);
        }
        sum_lo += __shfl_xor_sync(0xffffffffu, sum_lo, 1);
        sum_lo += __shfl_xor_sync(0xffffffffu, sum_lo, 2);
        sum_hi += __shfl_xor_sync(0xffffffffu, sum_hi, 1);
        sum_hi += __shfl_xor_sync(0xffffffffu, sum_hi, 2);

        float sc_lo = (m_lo == -INFINITY) ? 0.f : __expf(m_lo - mr_lo);
        float sc_hi = (m_hi == -INFINITY) ? 0.f : __expf(m_hi - mr_hi);
        l_lo = l_lo * sc_lo + sum_lo;
        l_hi = l_hi * sc_hi + sum_hi;
        m_lo = mn_lo;
        m_hi = mn_hi;

        #pragma unroll
        for (int j = 0; j < 8; j++) {
            o[j][0] *= sc_lo; o[j][1] *= sc_lo;
            o[j][2] *= sc_hi; o[j][3] *= sc_hi;
        }

        // ---- O += P V : S-fragment reused as A-fragment (keys permuted by
        //      pi(l)=2(l%4)+(l/4)); B = Vt rows d, adjacent keys -> LDS.64 ----
        #pragma unroll
        for (int j = 0; j < 8; j++) {
            const uint32_t a0 = cp[j][0];   // key 8j+2tg,   rows gr
            const uint32_t a1 = cp[j][2];   // key 8j+2tg,   rows gr+8
            const uint32_t a2 = cp[j][1];   // key 8j+2tg+1, rows gr
            const uint32_t a3 = cp[j][3];   // key 8j+2tg+1, rows gr+8
            #pragma unroll
            for (int jj = 0; jj < 8; jj++) {
                uint2 bb = *(const uint2*)&Vt[(8 * jj + gr) * AS2 + 8 * j + 2 * tg];
                mma_tf32(o[jj], a0, a1, a2, a3, bb.x, bb.y);
            }
        }
    }

    // ---- normalize + write out [L*B, E] at head offset ----
    float il_lo = 1.f / l_lo;
    float il_hi = 1.f / l_hi;
    #pragma unroll
    for (int j = 0; j < 8; j++) {
        float2 vlo = make_float2(o[j][0] * il_lo, o[j][1] * il_lo);
        *(float2*)(outp + (size_t)((m0 + q0 + gr) * BDIM + b) * EDIM
                   + hoff + 8 * j + 2 * tg) = vlo;
        float2 vhi = make_float2(o[j][2] * il_hi, o[j][3] * il_hi);
        *(float2*)(outp + (size_t)((m0 + q0 + gr + 8) * BDIM + b) * EDIM
                   + hoff + 8 * j + 2 * tg) = vhi;
    }
}

// ---------------------------------------------------------------------------
extern "C" void kernel_launch(void* const* d_in, const int* in_sizes, int n_in,
                              void* d_out, int out_size)
{
    const float* x    = (const float*)d_in[0];
    const float* win  = (const float*)d_in[1];
    const float* bin  = (const float*)d_in[2];
    const float* wout = (const float*)d_in[3];
    const float* bout = (const float*)d_in[4];
    const unsigned char* kpm = (const unsigned char*)d_in[5];
    float* out = (float*)d_out;

    float *qkv_ptr, *attn_ptr;
    cudaGetSymbolAddress((void**)&qkv_ptr,  g_qkv);
    cudaGetSymbolAddress((void**)&attn_ptr, g_attn);

    // 1) QKV projection (tf32 tensor; q pre-scaled by D^-0.5 in epilogue)
    {
        dim3 grid(E3 / 128, MROWS / 128);
        gemm_tf32<EDIM><<<grid, 256>>>(x, win, bin, qkv_ptr, E3, EDIM);
    }

    // 2) Flash attention (tf32 tensor, 2 CTAs/SM)
    {
        int smem = (128 * AS2 + 64 * AS2 + 64 * AS2) * (int)sizeof(uint32_t)
                   + 64 * (int)sizeof(float);   // 73984 B
        cudaFuncSetAttribute(attn_tf32, cudaFuncAttributeMaxDynamicSharedMemorySize, smem);
        dim3 grid(LDIM / 128, BDIM * HDIM);
        attn_tf32<<<grid, 256, smem>>>(qkv_ptr, kpm, attn_ptr);
    }

    // 3) Output projection (tf32 tensor)
    {
        dim3 grid(EDIM / 128, MROWS / 128);
        gemm_tf32<0><<<grid, 256>>>(attn_ptr, wout, bout, out, EDIM, EDIM);
    }
}